// round 1
// baseline (speedup 1.0000x reference)
#include <cuda_runtime.h>

#define N_NODES 50000
#define N_EDGES 800000
#define IN_DIM  256
#define HID     128
#define LEAKY   0.01f

// ---------------- scratch (static device allocations only) ----------------
__device__ __align__(16) float    g_z[N_NODES * HID];     // fc output per layer
__device__ __align__(16) float    g_h1[N_NODES * HID];    // layer-1 result (ELU applied)
__device__ __align__(16) float    g_acc[N_NODES * HID];   // scatter accumulator
__device__ float    g_s[N_NODES];                          // z . a[:D]
__device__ float    g_t[N_NODES];                          // z . a[D:]
__device__ unsigned g_m[N_NODES];                          // segment max (encoded)
__device__ float    g_denom[N_NODES];                      // segment sum of exp
__device__ float    g_e[N_EDGES];                          // leaky-relu'd logits

// order-preserving float <-> uint for atomicMax
__device__ __forceinline__ unsigned fenc(float f) {
    unsigned u = __float_as_uint(f);
    return (u & 0x80000000u) ? ~u : (u | 0x80000000u);
}
__device__ __forceinline__ float fdec(unsigned u) {
    u = (u & 0x80000000u) ? (u & 0x7fffffffu) : ~u;
    return __uint_as_float(u);
}

__device__ __forceinline__ float elu1(float x) {
    return x > 0.f ? x : (__expf(x) - 1.f);
}

// ---------------- init: zero accumulator / denom / max ----------------
__global__ void k_init() {
    int i = blockIdx.x * blockDim.x + threadIdx.x;
    if (i < N_NODES * HID) g_acc[i] = 0.f;
    if (i < N_NODES) { g_denom[i] = 0.f; g_m[i] = 0u; }  // 0 < fenc(any finite/-inf)
}

// ---------------- GEMM: z = X @ W^T + b, fused s/t epilogue ----------------
// X:[N, DIN] row-major, W:[128, DIN] row-major (both K-contiguous -> NT GEMM)
// Tile: 64 rows x 128 cols, BK=32. 256 threads, each 8x4 outputs.
template <int DIN>
__global__ void __launch_bounds__(256) k_gemm(
    const float* __restrict__ X,          // nullptr -> use g_h1
    const float* __restrict__ W,
    const float* __restrict__ bias,
    const float* __restrict__ a)          // length 2*HID
{
    __shared__ float Xs[64][33];
    __shared__ float Ws[128][33];

    const float* __restrict__ Xp = X ? X : g_h1;

    const int tid  = threadIdx.x;
    const int tx   = tid & 31;   // col group: cols tx*4 .. tx*4+3
    const int ty   = tid >> 5;   // row group: rows ty*8 .. ty*8+7
    const int row0 = blockIdx.x * 64;

    float acc[8][4];
#pragma unroll
    for (int i = 0; i < 8; i++)
#pragma unroll
        for (int j = 0; j < 4; j++) acc[i][j] = 0.f;

    for (int k0 = 0; k0 < DIN; k0 += 32) {
        // X tile: 64x32 = 512 float4, 2 per thread
#pragma unroll
        for (int v = 0; v < 2; v++) {
            int q  = tid + v * 256;
            int r  = q >> 3;
            int kq = (q & 7) << 2;
            int gr = row0 + r;
            float4 val = make_float4(0.f, 0.f, 0.f, 0.f);
            if (gr < N_NODES)
                val = *(const float4*)(Xp + (size_t)gr * DIN + k0 + kq);
            Xs[r][kq + 0] = val.x; Xs[r][kq + 1] = val.y;
            Xs[r][kq + 2] = val.z; Xs[r][kq + 3] = val.w;
        }
        // W tile: 128x32 = 1024 float4, 4 per thread
#pragma unroll
        for (int v = 0; v < 4; v++) {
            int q  = tid + v * 256;
            int c  = q >> 3;
            int kq = (q & 7) << 2;
            float4 val = *(const float4*)(W + (size_t)c * DIN + k0 + kq);
            Ws[c][kq + 0] = val.x; Ws[c][kq + 1] = val.y;
            Ws[c][kq + 2] = val.z; Ws[c][kq + 3] = val.w;
        }
        __syncthreads();

#pragma unroll
        for (int kk = 0; kk < 32; kk++) {
            float xr[8], wr[4];
#pragma unroll
            for (int i = 0; i < 8; i++) xr[i] = Xs[ty * 8 + i][kk];
#pragma unroll
            for (int j = 0; j < 4; j++) wr[j] = Ws[tx * 4 + j][kk];
#pragma unroll
            for (int i = 0; i < 8; i++)
#pragma unroll
                for (int j = 0; j < 4; j++)
                    acc[i][j] = fmaf(xr[i], wr[j], acc[i][j]);
        }
        __syncthreads();
    }

    // epilogue: add bias, write z, compute s = z.a[:128], t = z.a[128:]
    float b_[4], as_[4], ad_[4];
#pragma unroll
    for (int j = 0; j < 4; j++) {
        b_[j]  = bias[tx * 4 + j];
        as_[j] = a[tx * 4 + j];
        ad_[j] = a[HID + tx * 4 + j];
    }
#pragma unroll
    for (int i = 0; i < 8; i++) {
        int gr = row0 + ty * 8 + i;
        float zj[4];
        float sp = 0.f, tp = 0.f;
#pragma unroll
        for (int j = 0; j < 4; j++) {
            zj[j] = acc[i][j] + b_[j];
            sp = fmaf(zj[j], as_[j], sp);
            tp = fmaf(zj[j], ad_[j], tp);
        }
#pragma unroll
        for (int off = 16; off > 0; off >>= 1) {
            sp += __shfl_xor_sync(0xffffffffu, sp, off);
            tp += __shfl_xor_sync(0xffffffffu, tp, off);
        }
        if (gr < N_NODES) {
            *(float4*)(&g_z[(size_t)gr * HID + tx * 4]) =
                make_float4(zj[0], zj[1], zj[2], zj[3]);
            if (tx == 0) { g_s[gr] = sp; g_t[gr] = tp; }
        }
    }
}

// ---------------- edge pass 1: logits + segment max ----------------
__global__ void k_edge1(const int* __restrict__ src, const int* __restrict__ dst,
                        const float* __restrict__ abp) {
    int i = blockIdx.x * blockDim.x + threadIdx.x;
    if (i >= N_EDGES) return;
    float e = g_s[src[i]] + g_t[dst[i]] + abp[0];
    e = e > 0.f ? e : LEAKY * e;
    g_e[i] = e;
    atomicMax(&g_m[dst[i]], fenc(e));
}

// ---------------- edge pass 2: exp, denom sum, weighted scatter ----------------
// one warp per edge: acc[dst] += ex * z[src] (float4 gather + red.v4)
__global__ void __launch_bounds__(256) k_edge2(const int* __restrict__ src,
                                               const int* __restrict__ dst) {
    int wi = (blockIdx.x * blockDim.x + threadIdx.x) >> 5;
    if (wi >= N_EDGES) return;
    int lane = threadIdx.x & 31;

    int d  = dst[wi];
    int sn = src[wi];
    float ex = __expf(g_e[wi] - fdec(g_m[d]));

    if (lane == 0) atomicAdd(&g_denom[d], ex);

    float4 z4 = *(const float4*)(&g_z[(size_t)sn * HID + lane * 4]);
    float4 c  = make_float4(z4.x * ex, z4.y * ex, z4.z * ex, z4.w * ex);
    float* p  = &g_acc[(size_t)d * HID + lane * 4];
    asm volatile("red.global.add.v4.f32 [%0], {%1, %2, %3, %4};"
                 :: "l"(p), "f"(c.x), "f"(c.y), "f"(c.z), "f"(c.w)
                 : "memory");
}

// ---------------- node epilogue: normalize + ELU ----------------
__global__ void k_final(float* __restrict__ out) {   // nullptr -> g_h1
    int wi = (blockIdx.x * blockDim.x + threadIdx.x) >> 5;
    if (wi >= N_NODES) return;
    int lane = threadIdx.x & 31;
    float* __restrict__ op = out ? out : g_h1;

    float dn  = g_denom[wi];
    float inv = dn > 0.f ? 1.f / dn : 0.f;
    float4 a4 = *(const float4*)(&g_acc[(size_t)wi * HID + lane * 4]);
    float4 r;
    r.x = elu1(a4.x * inv);
    r.y = elu1(a4.y * inv);
    r.z = elu1(a4.z * inv);
    r.w = elu1(a4.w * inv);
    *(float4*)(&op[(size_t)wi * HID + lane * 4]) = r;
}

// ---------------- launch ----------------
extern "C" void kernel_launch(void* const* d_in, const int* in_sizes, int n_in,
                              void* d_out, int out_size) {
    const float* h   = (const float*)d_in[0];
    const int*   src = (const int*)d_in[1];
    const int*   dst = (const int*)d_in[2];
    const float* W1  = (const float*)d_in[3];
    const float* b1  = (const float*)d_in[4];
    const float* a1  = (const float*)d_in[5];
    const float* ab1 = (const float*)d_in[6];
    const float* W2  = (const float*)d_in[7];
    const float* b2  = (const float*)d_in[8];
    const float* a2  = (const float*)d_in[9];
    const float* ab2 = (const float*)d_in[10];
    float* out = (float*)d_out;

    const int initB = (N_NODES * HID + 255) / 256;
    const int gemmB = (N_NODES + 63) / 64;
    const int e1B   = (N_EDGES + 255) / 256;
    const int e2B   = (N_EDGES * 32 + 255) / 256;
    const int finB  = (N_NODES * 32 + 255) / 256;

    // ---- layer 1 ----
    k_init<<<initB, 256>>>();
    k_gemm<IN_DIM><<<gemmB, 256>>>(h, W1, b1, a1);
    k_edge1<<<e1B, 256>>>(src, dst, ab1);
    k_edge2<<<e2B, 256>>>(src, dst);
    k_final<<<finB, 256>>>(nullptr);           // -> g_h1 (with ELU)

    // ---- layer 2 ----
    k_init<<<initB, 256>>>();
    k_gemm<HID><<<gemmB, 256>>>(nullptr, W2, b2, a2);  // X = g_h1
    k_edge1<<<e1B, 256>>>(src, dst, ab2);
    k_edge2<<<e2B, 256>>>(src, dst);
    k_final<<<finB, 256>>>(out);
}

// round 2
// speedup vs baseline: 1.7193x; 1.7193x over previous
#include <cuda_runtime.h>

#define N_NODES 50000
#define N_EDGES 800000
#define IN_DIM  256
#define HID     128
#define LEAKY   0.01f

// ---------------- scratch (static device allocations only) ----------------
__device__ __align__(16) float g_z[N_NODES * HID];     // fc output per layer
__device__ __align__(16) float g_h1[N_NODES * HID];    // layer-1 result (ELU applied)
__device__ __align__(16) float g_acc[N_NODES * HID];   // scatter accumulator
__device__ float g_s[N_NODES];                          // z . a[:D]
__device__ float g_t[N_NODES];                          // z . a[D:]
__device__ float g_denom[N_NODES];                      // segment sum of exp

__device__ __forceinline__ float elu1(float x) {
    return x > 0.f ? x : (__expf(x) - 1.f);
}

// ---------------- init: zero accumulator / denom ----------------
__global__ void k_init() {
    int i = blockIdx.x * blockDim.x + threadIdx.x;
    if (i < N_NODES * HID) g_acc[i] = 0.f;
    if (i < N_NODES) g_denom[i] = 0.f;
}

// ---------------- GEMM: z = X @ W^T + b, fused s/t epilogue ----------------
// X:[N, DIN] row-major, W:[128, DIN] row-major (both K-contiguous -> NT GEMM)
// Tile: 64 rows x 128 cols, BK=32. 256 threads, each 8x4 outputs.
template <int DIN>
__global__ void __launch_bounds__(256) k_gemm(
    const float* __restrict__ X,          // nullptr -> use g_h1
    const float* __restrict__ W,
    const float* __restrict__ bias,
    const float* __restrict__ a)          // length 2*HID
{
    __shared__ float Xs[64][33];
    __shared__ float Ws[128][33];

    const float* __restrict__ Xp = X ? X : g_h1;

    const int tid  = threadIdx.x;
    const int tx   = tid & 31;   // col group: cols tx*4 .. tx*4+3
    const int ty   = tid >> 5;   // row group: rows ty*8 .. ty*8+7
    const int row0 = blockIdx.x * 64;

    float acc[8][4];
#pragma unroll
    for (int i = 0; i < 8; i++)
#pragma unroll
        for (int j = 0; j < 4; j++) acc[i][j] = 0.f;

    for (int k0 = 0; k0 < DIN; k0 += 32) {
        // X tile: 64x32 = 512 float4, 2 per thread
#pragma unroll
        for (int v = 0; v < 2; v++) {
            int q  = tid + v * 256;
            int r  = q >> 3;
            int kq = (q & 7) << 2;
            int gr = row0 + r;
            float4 val = make_float4(0.f, 0.f, 0.f, 0.f);
            if (gr < N_NODES)
                val = *(const float4*)(Xp + (size_t)gr * DIN + k0 + kq);
            Xs[r][kq + 0] = val.x; Xs[r][kq + 1] = val.y;
            Xs[r][kq + 2] = val.z; Xs[r][kq + 3] = val.w;
        }
        // W tile: 128x32 = 1024 float4, 4 per thread
#pragma unroll
        for (int v = 0; v < 4; v++) {
            int q  = tid + v * 256;
            int c  = q >> 3;
            int kq = (q & 7) << 2;
            float4 val = *(const float4*)(W + (size_t)c * DIN + k0 + kq);
            Ws[c][kq + 0] = val.x; Ws[c][kq + 1] = val.y;
            Ws[c][kq + 2] = val.z; Ws[c][kq + 3] = val.w;
        }
        __syncthreads();

#pragma unroll
        for (int kk = 0; kk < 32; kk++) {
            float xr[8], wr[4];
#pragma unroll
            for (int i = 0; i < 8; i++) xr[i] = Xs[ty * 8 + i][kk];
#pragma unroll
            for (int j = 0; j < 4; j++) wr[j] = Ws[tx * 4 + j][kk];
#pragma unroll
            for (int i = 0; i < 8; i++)
#pragma unroll
                for (int j = 0; j < 4; j++)
                    acc[i][j] = fmaf(xr[i], wr[j], acc[i][j]);
        }
        __syncthreads();
    }

    // epilogue: add bias, write z, compute s = z.a[:128], t = z.a[128:]
    float b_[4], as_[4], ad_[4];
#pragma unroll
    for (int j = 0; j < 4; j++) {
        b_[j]  = bias[tx * 4 + j];
        as_[j] = a[tx * 4 + j];
        ad_[j] = a[HID + tx * 4 + j];
    }
#pragma unroll
    for (int i = 0; i < 8; i++) {
        int gr = row0 + ty * 8 + i;
        float zj[4];
        float sp = 0.f, tp = 0.f;
#pragma unroll
        for (int j = 0; j < 4; j++) {
            zj[j] = acc[i][j] + b_[j];
            sp = fmaf(zj[j], as_[j], sp);
            tp = fmaf(zj[j], ad_[j], tp);
        }
#pragma unroll
        for (int off = 16; off > 0; off >>= 1) {
            sp += __shfl_xor_sync(0xffffffffu, sp, off);
            tp += __shfl_xor_sync(0xffffffffu, tp, off);
        }
        if (gr < N_NODES) {
            *(float4*)(&g_z[(size_t)gr * HID + tx * 4]) =
                make_float4(zj[0], zj[1], zj[2], zj[3]);
            if (tx == 0) { g_s[gr] = sp; g_t[gr] = tp; }
        }
    }
}

// ---------------- fused edge pass: exp(leaky(logit)), denom sum, scatter ----
// Softmax shift-invariance: max-subtraction dropped (|e| << 80, exp is safe).
// 2 edges per warp for MLP; per edge: LDG.128 z gather + RED.128 scatter.
__global__ void __launch_bounds__(256) k_edge(const int* __restrict__ src,
                                              const int* __restrict__ dst,
                                              const float* __restrict__ abp) {
    int w = (blockIdx.x * blockDim.x + threadIdx.x) >> 5;
    int e0 = w * 2;
    if (e0 >= N_EDGES) return;          // N_EDGES even -> e0+1 also valid
    int lane = threadIdx.x & 31;
    float ab = abp[0];

    int d0 = dst[e0],     sn0 = src[e0];
    int d1 = dst[e0 + 1], sn1 = src[e0 + 1];

    float e_a = g_s[sn0] + g_t[d0] + ab;
    float e_b = g_s[sn1] + g_t[d1] + ab;
    e_a = e_a > 0.f ? e_a : LEAKY * e_a;
    e_b = e_b > 0.f ? e_b : LEAKY * e_b;
    float ex0 = __expf(e_a);
    float ex1 = __expf(e_b);

    if (lane == 0) {
        atomicAdd(&g_denom[d0], ex0);
        atomicAdd(&g_denom[d1], ex1);
    }

    float4 z0 = *(const float4*)(&g_z[(size_t)sn0 * HID + lane * 4]);
    float4 z1 = *(const float4*)(&g_z[(size_t)sn1 * HID + lane * 4]);

    float* p0 = &g_acc[(size_t)d0 * HID + lane * 4];
    float* p1 = &g_acc[(size_t)d1 * HID + lane * 4];
    asm volatile("red.global.add.v4.f32 [%0], {%1, %2, %3, %4};"
                 :: "l"(p0), "f"(z0.x * ex0), "f"(z0.y * ex0),
                    "f"(z0.z * ex0), "f"(z0.w * ex0) : "memory");
    asm volatile("red.global.add.v4.f32 [%0], {%1, %2, %3, %4};"
                 :: "l"(p1), "f"(z1.x * ex1), "f"(z1.y * ex1),
                    "f"(z1.z * ex1), "f"(z1.w * ex1) : "memory");
}

// ---------------- node epilogue: normalize + ELU ----------------
__global__ void k_final(float* __restrict__ out) {   // nullptr -> g_h1
    int wi = (blockIdx.x * blockDim.x + threadIdx.x) >> 5;
    if (wi >= N_NODES) return;
    int lane = threadIdx.x & 31;
    float* __restrict__ op = out ? out : g_h1;

    float dn  = g_denom[wi];
    float inv = dn > 0.f ? 1.f / dn : 0.f;
    float4 a4 = *(const float4*)(&g_acc[(size_t)wi * HID + lane * 4]);
    float4 r;
    r.x = elu1(a4.x * inv);
    r.y = elu1(a4.y * inv);
    r.z = elu1(a4.z * inv);
    r.w = elu1(a4.w * inv);
    *(float4*)(&op[(size_t)wi * HID + lane * 4]) = r;
}

// ---------------- launch ----------------
extern "C" void kernel_launch(void* const* d_in, const int* in_sizes, int n_in,
                              void* d_out, int out_size) {
    const float* h   = (const float*)d_in[0];
    const int*   src = (const int*)d_in[1];
    const int*   dst = (const int*)d_in[2];
    const float* W1  = (const float*)d_in[3];
    const float* b1  = (const float*)d_in[4];
    const float* a1  = (const float*)d_in[5];
    const float* ab1 = (const float*)d_in[6];
    const float* W2  = (const float*)d_in[7];
    const float* b2  = (const float*)d_in[8];
    const float* a2  = (const float*)d_in[9];
    const float* ab2 = (const float*)d_in[10];
    float* out = (float*)d_out;

    const int initB = (N_NODES * HID + 255) / 256;
    const int gemmB = (N_NODES + 63) / 64;
    const int edgeB = (N_EDGES / 2 * 32 + 255) / 256;
    const int finB  = (N_NODES * 32 + 255) / 256;

    // ---- layer 1 ----
    k_init<<<initB, 256>>>();
    k_gemm<IN_DIM><<<gemmB, 256>>>(h, W1, b1, a1);
    k_edge<<<edgeB, 256>>>(src, dst, ab1);
    k_final<<<finB, 256>>>(nullptr);           // -> g_h1 (with ELU)

    // ---- layer 2 ----
    k_init<<<initB, 256>>>();
    k_gemm<HID><<<gemmB, 256>>>(nullptr, W2, b2, a2);  // X = g_h1
    k_edge<<<edgeB, 256>>>(src, dst, ab2);
    k_final<<<finB, 256>>>(out);
}

// round 3
// speedup vs baseline: 2.1935x; 1.2758x over previous
#include <cuda_runtime.h>

#define N_NODES 50000
#define N_EDGES 800000
#define IN_DIM  256
#define HID     128
#define LEAKY   0.01f

// ---------------- scratch (static device allocations only) ----------------
__device__ __align__(16) float g_z[N_NODES * HID];     // fc output per layer
__device__ __align__(16) float g_h1[N_NODES * HID];    // layer-1 result (ELU applied)
__device__ float g_s[N_NODES];                          // z . a[:D]
__device__ float g_t[N_NODES];                          // z . a[D:]
__device__ int   g_cnt[N_NODES];                        // in-degree histogram
__device__ int   g_cur[N_NODES];                        // fill cursors
__device__ int   g_off[N_NODES + 1];                    // CSR offsets
__device__ int   g_csr[N_EDGES];                        // src id per CSR slot

__device__ __forceinline__ float elu1(float x) {
    return x > 0.f ? x : (__expf(x) - 1.f);
}

// ================= CSR build (runs once per call, reused by both layers) ====
__global__ void k_zero() {
    int i = blockIdx.x * blockDim.x + threadIdx.x;
    if (i < N_NODES) { g_cnt[i] = 0; g_cur[i] = 0; }
}

__global__ void k_hist(const int* __restrict__ dst) {
    int i = blockIdx.x * blockDim.x + threadIdx.x;
    if (i < N_EDGES) atomicAdd(&g_cnt[dst[i]], 1);
}

// single-block exclusive scan over 50000 counts
__global__ void __launch_bounds__(1024) k_scan() {
    const int ITEMS = (N_NODES + 1023) / 1024;   // 49
    int t = threadIdx.x, lane = t & 31, wid = t >> 5;
    int base = t * ITEMS;

    int sum = 0;
#pragma unroll
    for (int i = 0; i < ITEMS; i++) {
        int idx = base + i;
        if (idx < N_NODES) sum += g_cnt[idx];
    }
    // inclusive warp scan of per-thread sums
    int v = sum;
#pragma unroll
    for (int off = 1; off < 32; off <<= 1) {
        int n = __shfl_up_sync(0xffffffffu, v, off);
        if (lane >= off) v += n;
    }
    __shared__ int wsum[32];
    if (lane == 31) wsum[wid] = v;
    __syncthreads();
    if (wid == 0) {
        int w = (lane < 32) ? wsum[lane] : 0;
#pragma unroll
        for (int off = 1; off < 32; off <<= 1) {
            int n = __shfl_up_sync(0xffffffffu, w, off);
            if (lane >= off) w += n;
        }
        wsum[lane] = w;
    }
    __syncthreads();
    int excl = v - sum + (wid > 0 ? wsum[wid - 1] : 0);

    int run = excl;
#pragma unroll
    for (int i = 0; i < ITEMS; i++) {
        int idx = base + i;
        if (idx < N_NODES) { g_off[idx] = run; run += g_cnt[idx]; }
    }
    if (t == 0) g_off[N_NODES] = N_EDGES;
}

__global__ void k_fill(const int* __restrict__ src, const int* __restrict__ dst) {
    int i = blockIdx.x * blockDim.x + threadIdx.x;
    if (i >= N_EDGES) return;
    int d = dst[i];
    int slot = g_off[d] + atomicAdd(&g_cur[d], 1);
    g_csr[slot] = src[i];
}

// ---------------- GEMM: z = X @ W^T + b, fused s/t epilogue ----------------
template <int DIN>
__global__ void __launch_bounds__(256) k_gemm(
    const float* __restrict__ X,          // nullptr -> use g_h1
    const float* __restrict__ W,
    const float* __restrict__ bias,
    const float* __restrict__ a)          // length 2*HID
{
    __shared__ float Xs[64][33];
    __shared__ float Ws[128][33];

    const float* __restrict__ Xp = X ? X : g_h1;

    const int tid  = threadIdx.x;
    const int tx   = tid & 31;
    const int ty   = tid >> 5;
    const int row0 = blockIdx.x * 64;

    float acc[8][4];
#pragma unroll
    for (int i = 0; i < 8; i++)
#pragma unroll
        for (int j = 0; j < 4; j++) acc[i][j] = 0.f;

    for (int k0 = 0; k0 < DIN; k0 += 32) {
#pragma unroll
        for (int v = 0; v < 2; v++) {
            int q  = tid + v * 256;
            int r  = q >> 3;
            int kq = (q & 7) << 2;
            int gr = row0 + r;
            float4 val = make_float4(0.f, 0.f, 0.f, 0.f);
            if (gr < N_NODES)
                val = *(const float4*)(Xp + (size_t)gr * DIN + k0 + kq);
            Xs[r][kq + 0] = val.x; Xs[r][kq + 1] = val.y;
            Xs[r][kq + 2] = val.z; Xs[r][kq + 3] = val.w;
        }
#pragma unroll
        for (int v = 0; v < 4; v++) {
            int q  = tid + v * 256;
            int c  = q >> 3;
            int kq = (q & 7) << 2;
            float4 val = *(const float4*)(W + (size_t)c * DIN + k0 + kq);
            Ws[c][kq + 0] = val.x; Ws[c][kq + 1] = val.y;
            Ws[c][kq + 2] = val.z; Ws[c][kq + 3] = val.w;
        }
        __syncthreads();

#pragma unroll
        for (int kk = 0; kk < 32; kk++) {
            float xr[8], wr[4];
#pragma unroll
            for (int i = 0; i < 8; i++) xr[i] = Xs[ty * 8 + i][kk];
#pragma unroll
            for (int j = 0; j < 4; j++) wr[j] = Ws[tx * 4 + j][kk];
#pragma unroll
            for (int i = 0; i < 8; i++)
#pragma unroll
                for (int j = 0; j < 4; j++)
                    acc[i][j] = fmaf(xr[i], wr[j], acc[i][j]);
        }
        __syncthreads();
    }

    float b_[4], as_[4], ad_[4];
#pragma unroll
    for (int j = 0; j < 4; j++) {
        b_[j]  = bias[tx * 4 + j];
        as_[j] = a[tx * 4 + j];
        ad_[j] = a[HID + tx * 4 + j];
    }
#pragma unroll
    for (int i = 0; i < 8; i++) {
        int gr = row0 + ty * 8 + i;
        float zj[4];
        float sp = 0.f, tp = 0.f;
#pragma unroll
        for (int j = 0; j < 4; j++) {
            zj[j] = acc[i][j] + b_[j];
            sp = fmaf(zj[j], as_[j], sp);
            tp = fmaf(zj[j], ad_[j], tp);
        }
#pragma unroll
        for (int off = 16; off > 0; off >>= 1) {
            sp += __shfl_xor_sync(0xffffffffu, sp, off);
            tp += __shfl_xor_sync(0xffffffffu, tp, off);
        }
        if (gr < N_NODES) {
            *(float4*)(&g_z[(size_t)gr * HID + tx * 4]) =
                make_float4(zj[0], zj[1], zj[2], zj[3]);
            if (tx == 0) { g_s[gr] = sp; g_t[gr] = tp; }
        }
    }
}

// ======== aggregate: per-dst gather, softmax weight, normalize, ELU ========
// One warp per dst node. Register accumulation — zero atomics.
// Softmax shift-invariance: max-subtraction dropped (|e| << 80, exp safe).
__global__ void __launch_bounds__(256) k_agg(const float* __restrict__ abp,
                                             float* __restrict__ out) {
    int node = (blockIdx.x * blockDim.x + threadIdx.x) >> 5;
    if (node >= N_NODES) return;
    int lane = threadIdx.x & 31;
    float* __restrict__ op = out ? out : g_h1;

    int   off0 = g_off[node];
    int   off1 = g_off[node + 1];
    float td   = g_t[node] + abp[0];

    float4 acc = make_float4(0.f, 0.f, 0.f, 0.f);
    float  den = 0.f;

    int j = off0;
    for (; j + 2 <= off1; j += 2) {
        int s0 = g_csr[j];
        int s1 = g_csr[j + 1];
        float e0 = g_s[s0] + td;
        float e1 = g_s[s1] + td;
        e0 = e0 > 0.f ? e0 : LEAKY * e0;
        e1 = e1 > 0.f ? e1 : LEAKY * e1;
        float ex0 = __expf(e0);
        float ex1 = __expf(e1);
        float4 z0 = *(const float4*)(&g_z[(size_t)s0 * HID + lane * 4]);
        float4 z1 = *(const float4*)(&g_z[(size_t)s1 * HID + lane * 4]);
        acc.x = fmaf(ex0, z0.x, acc.x); acc.y = fmaf(ex0, z0.y, acc.y);
        acc.z = fmaf(ex0, z0.z, acc.z); acc.w = fmaf(ex0, z0.w, acc.w);
        acc.x = fmaf(ex1, z1.x, acc.x); acc.y = fmaf(ex1, z1.y, acc.y);
        acc.z = fmaf(ex1, z1.z, acc.z); acc.w = fmaf(ex1, z1.w, acc.w);
        den += ex0 + ex1;
    }
    if (j < off1) {
        int s0 = g_csr[j];
        float e0 = g_s[s0] + td;
        e0 = e0 > 0.f ? e0 : LEAKY * e0;
        float ex0 = __expf(e0);
        float4 z0 = *(const float4*)(&g_z[(size_t)s0 * HID + lane * 4]);
        acc.x = fmaf(ex0, z0.x, acc.x); acc.y = fmaf(ex0, z0.y, acc.y);
        acc.z = fmaf(ex0, z0.z, acc.z); acc.w = fmaf(ex0, z0.w, acc.w);
        den += ex0;
    }

    float inv = den > 0.f ? 1.f / den : 0.f;
    float4 r;
    r.x = elu1(acc.x * inv);
    r.y = elu1(acc.y * inv);
    r.z = elu1(acc.z * inv);
    r.w = elu1(acc.w * inv);
    *(float4*)(&op[(size_t)node * HID + lane * 4]) = r;
}

// ---------------- launch ----------------
extern "C" void kernel_launch(void* const* d_in, const int* in_sizes, int n_in,
                              void* d_out, int out_size) {
    const float* h   = (const float*)d_in[0];
    const int*   src = (const int*)d_in[1];
    const int*   dst = (const int*)d_in[2];
    const float* W1  = (const float*)d_in[3];
    const float* b1  = (const float*)d_in[4];
    const float* a1  = (const float*)d_in[5];
    const float* ab1 = (const float*)d_in[6];
    const float* W2  = (const float*)d_in[7];
    const float* b2  = (const float*)d_in[8];
    const float* a2  = (const float*)d_in[9];
    const float* ab2 = (const float*)d_in[10];
    float* out = (float*)d_out;

    const int zeroB = (N_NODES + 255) / 256;
    const int edgeB = (N_EDGES + 255) / 256;
    const int gemmB = (N_NODES + 63) / 64;
    const int aggB  = (N_NODES * 32 + 255) / 256;

    // ---- CSR build (shared by both layers) ----
    k_zero<<<zeroB, 256>>>();
    k_hist<<<edgeB, 256>>>(dst);
    k_scan<<<1, 1024>>>();
    k_fill<<<edgeB, 256>>>(src, dst);

    // ---- layer 1 ----
    k_gemm<IN_DIM><<<gemmB, 256>>>(h, W1, b1, a1);
    k_agg<<<aggB, 256>>>(ab1, nullptr);        // -> g_h1 (ELU applied)

    // ---- layer 2 ----
    k_gemm<HID><<<gemmB, 256>>>(nullptr, W2, b2, a2);   // X = g_h1
    k_agg<<<aggB, 256>>>(ab2, out);
}

// round 5
// speedup vs baseline: 2.7998x; 1.2764x over previous
#include <cuda_runtime.h>
#include <cuda_bf16.h>
#include <cstdint>

#define N_NODES 50000
#define N_EDGES 800000
#define IN_DIM  256
#define HID     128
#define LEAKY   0.01f

// ---------------- scratch (static device allocations only) ----------------
__device__ __align__(16) float g_z[N_NODES * HID];     // fc output per layer
__device__ __align__(16) float g_h1[N_NODES * HID];    // layer-1 result (ELU applied)
__device__ float g_s[N_NODES];                          // z . a[:D]
__device__ float g_t[N_NODES];                          // z . a[D:]
__device__ int   g_cnt[N_NODES];                        // in-degree histogram
__device__ int   g_cur[N_NODES];                        // fill cursors
__device__ int   g_off[N_NODES + 1];                    // CSR offsets
__device__ int   g_csr[N_EDGES];                        // src id per CSR slot

__device__ __forceinline__ float elu1(float x) {
    return x > 0.f ? x : (__expf(x) - 1.f);
}

// ================= CSR build (once per call, reused by both layers) ========
__global__ void k_zero() {
    int i = blockIdx.x * blockDim.x + threadIdx.x;
    if (i < N_NODES) { g_cnt[i] = 0; g_cur[i] = 0; }
}

__global__ void k_hist(const int* __restrict__ dst) {
    int i = blockIdx.x * blockDim.x + threadIdx.x;
    if (i < N_EDGES) atomicAdd(&g_cnt[dst[i]], 1);
}

__global__ void __launch_bounds__(1024) k_scan() {
    const int ITEMS = (N_NODES + 1023) / 1024;   // 49
    int t = threadIdx.x, lane = t & 31, wid = t >> 5;
    int base = t * ITEMS;

    int sum = 0;
#pragma unroll
    for (int i = 0; i < ITEMS; i++) {
        int idx = base + i;
        if (idx < N_NODES) sum += g_cnt[idx];
    }
    int v = sum;
#pragma unroll
    for (int off = 1; off < 32; off <<= 1) {
        int n = __shfl_up_sync(0xffffffffu, v, off);
        if (lane >= off) v += n;
    }
    __shared__ int wsum[32];
    if (lane == 31) wsum[wid] = v;
    __syncthreads();
    if (wid == 0) {
        int w = wsum[lane];
#pragma unroll
        for (int off = 1; off < 32; off <<= 1) {
            int n = __shfl_up_sync(0xffffffffu, w, off);
            if (lane >= off) w += n;
        }
        wsum[lane] = w;
    }
    __syncthreads();
    int excl = v - sum + (wid > 0 ? wsum[wid - 1] : 0);

    int run = excl;
#pragma unroll
    for (int i = 0; i < ITEMS; i++) {
        int idx = base + i;
        if (idx < N_NODES) { g_off[idx] = run; run += g_cnt[idx]; }
    }
    if (t == 0) g_off[N_NODES] = N_EDGES;
}

__global__ void k_fill(const int* __restrict__ src, const int* __restrict__ dst) {
    int i = blockIdx.x * blockDim.x + threadIdx.x;
    if (i >= N_EDGES) return;
    int d = dst[i];
    int slot = g_off[d] + atomicAdd(&g_cur[d], 1);
    g_csr[slot] = src[i];
}

// ============ tensor-core GEMM: z = X @ W^T + b  (bf16 hi/lo split) ========
// X:[N,K] row-major, W:[128,K] row-major. Block tile 128x128, BK=32.
// 8 warps: warpM = wid&3 (32 rows each), warpN = wid>>2 (64 cols each).
// 3-product split: hi*hi + hi*lo + lo*hi (fp32 accum) ~ 17-bit mantissa.

__device__ __forceinline__ void mma16816(float d[4], const uint32_t a[4],
                                         const uint32_t b[2]) {
    asm volatile(
        "mma.sync.aligned.m16n8k16.row.col.f32.bf16.bf16.f32 "
        "{%0,%1,%2,%3}, {%4,%5,%6,%7}, {%8,%9}, {%0,%1,%2,%3};"
        : "+f"(d[0]), "+f"(d[1]), "+f"(d[2]), "+f"(d[3])
        : "r"(a[0]), "r"(a[1]), "r"(a[2]), "r"(a[3]), "r"(b[0]), "r"(b[1]));
}

#define SSTR 40   // smem K-stride in bf16 elems (80B) -> conflict-free frags

template <int K>
__global__ void __launch_bounds__(256) k_gemm_tc(
    const float* __restrict__ X,          // nullptr -> g_h1
    const float* __restrict__ W,
    const float* __restrict__ bias,
    const float* __restrict__ a)          // length 2*HID
{
    __shared__ __nv_bfloat16 sAh[128][SSTR], sAl[128][SSTR];
    __shared__ __nv_bfloat16 sBh[128][SSTR], sBl[128][SSTR];
    __shared__ float s_part[2][128], t_part[2][128];

    const float* __restrict__ Xp = X ? X : g_h1;

    const int tid   = threadIdx.x;
    const int wid   = tid >> 5;
    const int lane  = tid & 31;
    const int g     = lane >> 2;          // group id 0..7
    const int tig   = lane & 3;           // thread-in-group 0..3
    const int warpM = wid & 3;            // 0..3  -> 32 rows
    const int warpN = wid >> 2;           // 0..1  -> 64 cols
    const int row0  = blockIdx.x * 128;

    float acc[2][8][4];
#pragma unroll
    for (int mt = 0; mt < 2; mt++)
#pragma unroll
        for (int nt = 0; nt < 8; nt++)
#pragma unroll
            for (int r = 0; r < 4; r++) acc[mt][nt][r] = 0.f;

    for (int k0 = 0; k0 < K; k0 += 32) {
        // load + split X tile (128x32) and W tile (128x32): 4 float4/thread
#pragma unroll
        for (int v = 0; v < 4; v++) {
            int q  = tid + v * 256;
            int r  = q >> 3;
            int kq = (q & 7) << 2;
            int gr = row0 + r;
            float4 xv = make_float4(0.f, 0.f, 0.f, 0.f);
            if (gr < N_NODES)
                xv = *(const float4*)(Xp + (size_t)gr * K + k0 + kq);
            float4 wv = *(const float4*)(W + (size_t)r * K + k0 + kq);
            const float* xs = &xv.x;
            const float* ws = &wv.x;
#pragma unroll
            for (int i = 0; i < 4; i++) {
                float x = xs[i];
                __nv_bfloat16 hx = __float2bfloat16(x);
                sAh[r][kq + i] = hx;
                sAl[r][kq + i] = __float2bfloat16(x - __bfloat162float(hx));
                float w = ws[i];
                __nv_bfloat16 hw = __float2bfloat16(w);
                sBh[r][kq + i] = hw;
                sBl[r][kq + i] = __float2bfloat16(w - __bfloat162float(hw));
            }
        }
        __syncthreads();

#pragma unroll
        for (int ks = 0; ks < 32; ks += 16) {
            // A fragments: 2 m-tiles, hi+lo
            uint32_t ah[2][4], al[2][4];
#pragma unroll
            for (int mt = 0; mt < 2; mt++) {
                int r = warpM * 32 + mt * 16 + g;
                int kk = ks + tig * 2;
                ah[mt][0] = *(const uint32_t*)&sAh[r][kk];
                ah[mt][1] = *(const uint32_t*)&sAh[r + 8][kk];
                ah[mt][2] = *(const uint32_t*)&sAh[r][kk + 8];
                ah[mt][3] = *(const uint32_t*)&sAh[r + 8][kk + 8];
                al[mt][0] = *(const uint32_t*)&sAl[r][kk];
                al[mt][1] = *(const uint32_t*)&sAl[r + 8][kk];
                al[mt][2] = *(const uint32_t*)&sAl[r][kk + 8];
                al[mt][3] = *(const uint32_t*)&sAl[r + 8][kk + 8];
            }
            // B fragments: 8 n-tiles, hi+lo
            uint32_t bh[8][2], bl[8][2];
#pragma unroll
            for (int nt = 0; nt < 8; nt++) {
                int c = warpN * 64 + nt * 8 + g;
                int kk = ks + tig * 2;
                bh[nt][0] = *(const uint32_t*)&sBh[c][kk];
                bh[nt][1] = *(const uint32_t*)&sBh[c][kk + 8];
                bl[nt][0] = *(const uint32_t*)&sBl[c][kk];
                bl[nt][1] = *(const uint32_t*)&sBl[c][kk + 8];
            }
#pragma unroll
            for (int mt = 0; mt < 2; mt++)
#pragma unroll
                for (int nt = 0; nt < 8; nt++) {
                    mma16816(acc[mt][nt], ah[mt], bh[nt]);
                    mma16816(acc[mt][nt], ah[mt], bl[nt]);
                    mma16816(acc[mt][nt], al[mt], bh[nt]);
                }
        }
        __syncthreads();
    }

    // ---- epilogue: bias, store z, per-row s/t dots ----
    float sp[2][2] = {{0.f, 0.f}, {0.f, 0.f}};   // [mt][row half]
    float tp[2][2] = {{0.f, 0.f}, {0.f, 0.f}};
#pragma unroll
    for (int mt = 0; mt < 2; mt++) {
        int rA = row0 + warpM * 32 + mt * 16 + g;
        int rB = rA + 8;
#pragma unroll
        for (int nt = 0; nt < 8; nt++) {
            int c0 = warpN * 64 + nt * 8 + tig * 2;
            float bb0 = bias[c0], bb1 = bias[c0 + 1];
            float a0s = a[c0], a1s = a[c0 + 1];
            float a0d = a[HID + c0], a1d = a[HID + c0 + 1];
            float v0 = acc[mt][nt][0] + bb0;
            float v1 = acc[mt][nt][1] + bb1;
            float v2 = acc[mt][nt][2] + bb0;
            float v3 = acc[mt][nt][3] + bb1;
            if (rA < N_NODES)
                *(float2*)(&g_z[(size_t)rA * HID + c0]) = make_float2(v0, v1);
            if (rB < N_NODES)
                *(float2*)(&g_z[(size_t)rB * HID + c0]) = make_float2(v2, v3);
            sp[mt][0] = fmaf(v0, a0s, fmaf(v1, a1s, sp[mt][0]));
            tp[mt][0] = fmaf(v0, a0d, fmaf(v1, a1d, tp[mt][0]));
            sp[mt][1] = fmaf(v2, a0s, fmaf(v3, a1s, sp[mt][1]));
            tp[mt][1] = fmaf(v2, a0d, fmaf(v3, a1d, tp[mt][1]));
        }
    }
    // quad reduce (row depends only on g) then cross-n-warp combine via smem
#pragma unroll
    for (int mt = 0; mt < 2; mt++)
#pragma unroll
        for (int hh = 0; hh < 2; hh++) {
            float s = sp[mt][hh], t = tp[mt][hh];
            s += __shfl_xor_sync(0xffffffffu, s, 1);
            s += __shfl_xor_sync(0xffffffffu, s, 2);
            t += __shfl_xor_sync(0xffffffffu, t, 1);
            t += __shfl_xor_sync(0xffffffffu, t, 2);
            if (tig == 0) {
                int lr = warpM * 32 + mt * 16 + hh * 8 + g;
                s_part[warpN][lr] = s;
                t_part[warpN][lr] = t;
            }
        }
    __syncthreads();
    if (tid < 128) {
        int gr = row0 + tid;
        if (gr < N_NODES) {
            g_s[gr] = s_part[0][tid] + s_part[1][tid];
            g_t[gr] = t_part[0][tid] + t_part[1][tid];
        }
    }
}

// ======== aggregate: per-dst gather, softmax weight, normalize, ELU ========
// One warp per dst node, register accumulation, no atomics.
// Max-subtraction dropped (|e| << 80, exp safe; softmax shift-invariant).
__global__ void __launch_bounds__(256) k_agg(const float* __restrict__ abp,
                                             float* __restrict__ out) {
    int node = (blockIdx.x * blockDim.x + threadIdx.x) >> 5;
    if (node >= N_NODES) return;
    int lane = threadIdx.x & 31;
    float* __restrict__ op = out ? out : g_h1;

    int   off0 = g_off[node];
    int   off1 = g_off[node + 1];
    float td   = g_t[node] + abp[0];

    float4 acc = make_float4(0.f, 0.f, 0.f, 0.f);
    float  den = 0.f;

    int j = off0;
    for (; j + 2 <= off1; j += 2) {
        int s0 = g_csr[j];
        int s1 = g_csr[j + 1];
        float e0 = g_s[s0] + td;
        float e1 = g_s[s1] + td;
        e0 = e0 > 0.f ? e0 : LEAKY * e0;
        e1 = e1 > 0.f ? e1 : LEAKY * e1;
        float ex0 = __expf(e0);
        float ex1 = __expf(e1);
        float4 z0 = *(const float4*)(&g_z[(size_t)s0 * HID + lane * 4]);
        float4 z1 = *(const float4*)(&g_z[(size_t)s1 * HID + lane * 4]);
        acc.x = fmaf(ex0, z0.x, acc.x); acc.y = fmaf(ex0, z0.y, acc.y);
        acc.z = fmaf(ex0, z0.z, acc.z); acc.w = fmaf(ex0, z0.w, acc.w);
        acc.x = fmaf(ex1, z1.x, acc.x); acc.y = fmaf(ex1, z1.y, acc.y);
        acc.z = fmaf(ex1, z1.z, acc.z); acc.w = fmaf(ex1, z1.w, acc.w);
        den += ex0 + ex1;
    }
    if (j < off1) {
        int s0 = g_csr[j];
        float e0 = g_s[s0] + td;
        e0 = e0 > 0.f ? e0 : LEAKY * e0;
        float ex0 = __expf(e0);
        float4 z0 = *(const float4*)(&g_z[(size_t)s0 * HID + lane * 4]);
        acc.x = fmaf(ex0, z0.x, acc.x); acc.y = fmaf(ex0, z0.y, acc.y);
        acc.z = fmaf(ex0, z0.z, acc.z); acc.w = fmaf(ex0, z0.w, acc.w);
        den += ex0;
    }

    float inv = den > 0.f ? 1.f / den : 0.f;
    float4 r;
    r.x = elu1(acc.x * inv);
    r.y = elu1(acc.y * inv);
    r.z = elu1(acc.z * inv);
    r.w = elu1(acc.w * inv);
    *(float4*)(&op[(size_t)node * HID + lane * 4]) = r;
}

// ---------------- launch ----------------
extern "C" void kernel_launch(void* const* d_in, const int* in_sizes, int n_in,
                              void* d_out, int out_size) {
    const float* h   = (const float*)d_in[0];
    const int*   src = (const int*)d_in[1];
    const int*   dst = (const int*)d_in[2];
    const float* W1  = (const float*)d_in[3];
    const float* b1  = (const float*)d_in[4];
    const float* a1  = (const float*)d_in[5];
    const float* ab1 = (const float*)d_in[6];
    const float* W2  = (const float*)d_in[7];
    const float* b2  = (const float*)d_in[8];
    const float* a2  = (const float*)d_in[9];
    const float* ab2 = (const float*)d_in[10];
    float* out = (float*)d_out;

    const int zeroB = (N_NODES + 255) / 256;
    const int edgeB = (N_EDGES + 255) / 256;
    const int gemmB = (N_NODES + 127) / 128;
    const int aggB  = (N_NODES * 32 + 255) / 256;

    // ---- CSR build (shared by both layers) ----
    k_zero<<<zeroB, 256>>>();
    k_hist<<<edgeB, 256>>>(dst);
    k_scan<<<1, 1024>>>();
    k_fill<<<edgeB, 256>>>(src, dst);

    // ---- layer 1 ----
    k_gemm_tc<IN_DIM><<<gemmB, 256>>>(h, W1, b1, a1);
    k_agg<<<aggB, 256>>>(ab1, nullptr);        // -> g_h1 (ELU applied)

    // ---- layer 2 ----
    k_gemm_tc<HID><<<gemmB, 256>>>(nullptr, W2, b2, a2);   // X = g_h1
    k_agg<<<aggB, 256>>>(ab2, out);
}